// round 3
// baseline (speedup 1.0000x reference)
#include <cuda_runtime.h>
#include <cuda_fp16.h>

#define BB 64
#define II 4096
#define CC 32
#define DD 16
#define KD 16

#define NCHUNK 32      // i-chunks for routing partials
#define RITERS 16      // i's per warp per routing CTA: NCHUNK*8*RITERS == II
#define NI 4           // i's per uhat CTA
#define UGRID (II/NI)  // 1024

#define WP 20          // Wsm pitch (floats)  -> bank-conflict-free fragment loads
#define XP 20          // xsm pitch (floats)
#define OP 520         // Osm pitch (halves) -> 260 words (==4 mod 32): clean writes+reads

// smem: W (512*20 f32) + x (64*20 f32) + O (64*520 f16)
#define SMEM_UHAT ((512*WP + BB*XP) * 4 + BB*OP * 2)

// Scratch (static device globals; no runtime allocation)
__device__ __half g_uhat[(size_t)BB * II * CC * DD];   // 268 MB, layout [b][i][c*16+D]
__device__ float  g_spart[NCHUNK][BB * CC * DD];       // partial s, layout [chunk][b][D][c]
__device__ float  g_V[BB * CC * DD];                   // Vsum, layout [b][c][D]

__global__ void dummy_kernel() {}

static __device__ __forceinline__ unsigned f2tf32(float a) {
    unsigned r;
    asm("cvt.rna.tf32.f32 %0, %1;" : "=r"(r) : "f"(a));
    return r;
}

// ---------- pass 0 (tensor cores): u_hat[b,i,n] = sum_d x[b,i,d] * W[i,n,d], fp16 out ----
// CTA = 512 threads = 16 warps, NI i's. warp = (mt, ng): mt -> b-tile 16*mt..+15,
// ng -> n range 128*ng..+127 (16 N-tiles of 8). m16n8k8 tf32 mma, A=x (row), B=W (col).
__global__ __launch_bounds__(512, 1) void uhat_kernel(
    const float* __restrict__ x, const float* __restrict__ w) {
    extern __shared__ char smem[];
    float*  Wsm = (float*)smem;                    // [n*WP + d]
    float*  xsm = Wsm + 512 * WP;                  // [b*XP + d]
    __half* Osm = (__half*)(xsm + BB * XP);        // [b*OP + n]

    const int tid  = threadIdx.x;
    const int warp = tid >> 5;
    const int l    = tid & 31;
    const int lr   = l >> 2;     // 0..7
    const int lc   = l & 3;      // 0..3
    const int mt   = warp >> 2;  // 0..3
    const int ng   = warp & 3;   // 0..3
    const int ib   = blockIdx.x * NI;

    float4 wreg[4];
    float  xreg[2];

    // preload tile for i = ib
    {
        const float4* w4 = (const float4*)(w + (size_t)ib * 8192);
        #pragma unroll
        for (int q = 0; q < 4; q++) wreg[q] = w4[tid + q * 512];
        #pragma unroll
        for (int q = 0; q < 2; q++) {
            int e = tid + q * 512;
            xreg[q] = x[((size_t)(e >> 4)) * (II * KD) + (size_t)ib * KD + (e & 15)];
        }
    }

    for (int j = 0; j < NI; j++) {
        __syncthreads();   // prior iter's Osm reads / smem reads complete
        // store W (tf32-converted) into Wsm, pitch 20
        #pragma unroll
        for (int q = 0; q < 4; q++) {
            int t_ = tid + q * 512;
            int n  = t_ >> 2, d0 = (t_ & 3) * 4;
            float4 cv;
            cv.x = __uint_as_float(f2tf32(wreg[q].x));
            cv.y = __uint_as_float(f2tf32(wreg[q].y));
            cv.z = __uint_as_float(f2tf32(wreg[q].z));
            cv.w = __uint_as_float(f2tf32(wreg[q].w));
            *(float4*)&Wsm[n * WP + d0] = cv;
        }
        #pragma unroll
        for (int q = 0; q < 2; q++) {
            int e = tid + q * 512;
            xsm[(e >> 4) * XP + (e & 15)] = __uint_as_float(f2tf32(xreg[q]));
        }
        __syncthreads();

        // prefetch next i's tile (overlaps the mma phase)
        if (j + 1 < NI) {
            int ii = ib + j + 1;
            const float4* w4 = (const float4*)(w + (size_t)ii * 8192);
            #pragma unroll
            for (int q = 0; q < 4; q++) wreg[q] = w4[tid + q * 512];
            #pragma unroll
            for (int q = 0; q < 2; q++) {
                int e = tid + q * 512;
                xreg[q] = x[((size_t)(e >> 4)) * (II * KD) + (size_t)ii * KD + (e & 15)];
            }
        }

        // ---- tensor-core GEMM: 1 M-tile x 16 N-tiles per warp, K=16 = 2 k-steps ----
        float c[16][4];
        #pragma unroll
        for (int nt = 0; nt < 16; nt++)
            { c[nt][0] = 0.f; c[nt][1] = 0.f; c[nt][2] = 0.f; c[nt][3] = 0.f; }

        #pragma unroll
        for (int ks = 0; ks < 2; ks++) {
            int xoff = (16 * mt + lr) * XP + 8 * ks + lc;
            unsigned a0 = __float_as_uint(xsm[xoff]);
            unsigned a1 = __float_as_uint(xsm[xoff + 8 * XP]);
            unsigned a2 = __float_as_uint(xsm[xoff + 4]);
            unsigned a3 = __float_as_uint(xsm[xoff + 8 * XP + 4]);
            #pragma unroll
            for (int nt = 0; nt < 16; nt++) {
                int woff = (128 * ng + 8 * nt + lr) * WP + 8 * ks + lc;
                unsigned b0 = __float_as_uint(Wsm[woff]);
                unsigned b1 = __float_as_uint(Wsm[woff + 4]);
                asm volatile(
                    "mma.sync.aligned.m16n8k8.row.col.f32.tf32.tf32.f32 "
                    "{%0,%1,%2,%3}, {%4,%5,%6,%7}, {%8,%9}, {%0,%1,%2,%3};"
                    : "+f"(c[nt][0]), "+f"(c[nt][1]), "+f"(c[nt][2]), "+f"(c[nt][3])
                    : "r"(a0), "r"(a1), "r"(a2), "r"(a3), "r"(b0), "r"(b1));
            }
        }

        // ---- epilogue: fragments -> Osm (fp16, [b][n], pitch 520) ----
        {
            int r0 = 16 * mt + lr, r1 = r0 + 8;
            #pragma unroll
            for (int nt = 0; nt < 16; nt++) {
                int n = 128 * ng + 8 * nt + 2 * lc;
                *(__half2*)&Osm[r0 * OP + n] = __floats2half2_rn(c[nt][0], c[nt][1]);
                *(__half2*)&Osm[r1 * OP + n] = __floats2half2_rn(c[nt][2], c[nt][3]);
            }
        }
        __syncthreads();

        // ---- coalesced store: thread (b = tid&63, ch = tid>>6) moves 128 B ----
        {
            const int i  = ib + j;
            const int b  = tid & 63;
            const int ch = tid >> 6;           // 0..7
            __half* dst = g_uhat + ((size_t)b * II + i) * (CC * DD);
            #pragma unroll
            for (int jj = 0; jj < 8; jj++) {
                int ho = ch * 64 + jj * 8;
                uint4 v = *(uint4*)&Osm[b * OP + ho];
                *(uint4*)&dst[ho] = v;
            }
        }
    }
}

// ---------- routing pass: s[b,c,D] = sum_i softmax_c(u . Vsum) * u ----------
__global__ __launch_bounds__(256) void routing_kernel(int pass1) {
    const int b     = blockIdx.y;
    const int chunk = blockIdx.x;
    const int warp  = threadIdx.x >> 5;
    const int c     = threadIdx.x & 31;

    float V[DD];
    if (!pass1) {
        #pragma unroll
        for (int D = 0; D < DD; D++) V[D] = g_V[(b * CC + c) * DD + D];
    }

    float sacc[DD];
    #pragma unroll
    for (int D = 0; D < DD; D++) sacc[D] = 0.0f;

    const int i0 = chunk * (8 * RITERS) + warp * RITERS;
    const uint4* p = (const uint4*)(g_uhat + ((size_t)b * II + i0) * (CC * DD)) + c * 2;

    uint4 q0 = p[0];
    uint4 q1 = p[1];

    #pragma unroll 4
    for (int k = 0; k < RITERS; k++) {
        uint4 n0 = q0, n1 = q1;
        if (k + 1 < RITERS) {
            n0 = p[(k + 1) * 64];
            n1 = p[(k + 1) * 64 + 1];
        }

        float u[DD];
        unsigned rr[8] = {q0.x, q0.y, q0.z, q0.w, q1.x, q1.y, q1.z, q1.w};
        #pragma unroll
        for (int pp = 0; pp < 8; pp++) {
            __half2 h = *reinterpret_cast<__half2*>(&rr[pp]);
            float2 f = __half22float2(h);
            u[2 * pp]     = f.x;
            u[2 * pp + 1] = f.y;
        }

        float cij;
        if (pass1) {
            cij = 1.0f / 32.0f;
        } else {
            float logit = 0.0f;
            #pragma unroll
            for (int D = 0; D < DD; D++) logit = fmaf(u[D], V[D], logit);
            float m = logit;
            #pragma unroll
            for (int off = 16; off > 0; off >>= 1)
                m = fmaxf(m, __shfl_xor_sync(0xffffffffu, m, off));
            float e = __expf(logit - m);
            float ssum = e;
            #pragma unroll
            for (int off = 16; off > 0; off >>= 1)
                ssum += __shfl_xor_sync(0xffffffffu, ssum, off);
            cij = e / ssum;
        }

        #pragma unroll
        for (int D = 0; D < DD; D++) sacc[D] = fmaf(cij, u[D], sacc[D]);

        q0 = n0; q1 = n1;
    }

    __shared__ float red[8][CC * DD];
    #pragma unroll
    for (int D = 0; D < DD; D++) red[warp][D * 32 + c] = sacc[D];
    __syncthreads();

    for (int t = threadIdx.x; t < CC * DD; t += 256) {
        float v = 0.0f;
        #pragma unroll
        for (int wq = 0; wq < 8; wq++) v += red[wq][t];
        g_spart[chunk][b * (CC * DD) + t] = v;   // [chunk][b][D][c]
    }
}

// ---------- squash: one thread per (b,c,D); 16-lane shfl for |s|^2 ----------
__global__ void squash_kernel(float* __restrict__ out, int pass) {
    int t = blockIdx.x * blockDim.x + threadIdx.x;   // (b,c,D), D fastest
    int bc = t >> 4, D = t & 15;
    int b = bc >> 5, c = bc & 31;
    int addr = b * (CC * DD) + D * 32 + c;           // [b][D][c] partial layout

    float s = 0.0f;
    #pragma unroll
    for (int ch = 0; ch < NCHUNK; ch++) s += g_spart[ch][addr];

    float sq = s * s;
    #pragma unroll
    for (int off = 1; off < 16; off <<= 1)
        sq += __shfl_xor_sync(0xffffffffu, sq, off);

    float f = 1.0f / ((1.0f + sq) * sqrtf(sq + 1e-9f));
    float v = s * f;

    if (pass == 0)      g_V[t] = v;
    else if (pass == 1) g_V[t] += v;
    else                out[t] = v;
}

extern "C" void kernel_launch(void* const* d_in, const int* in_sizes, int n_in,
                              void* d_out, int out_size) {
    const float* x = (const float*)d_in[0];
    const float* w = (const float*)d_in[1];
    float* out = (float*)d_out;

    cudaFuncSetAttribute(uhat_kernel, cudaFuncAttributeMaxDynamicSharedMemorySize,
                         SMEM_UHAT);

    // five dummies shift the ncu -s 5 -c 1 window onto uhat_kernel (launch #6)
    for (int q = 0; q < 5; q++) dummy_kernel<<<1, 32>>>();

    uhat_kernel<<<UGRID, 512, SMEM_UHAT>>>(x, w);

    routing_kernel<<<dim3(NCHUNK, BB), 256>>>(1);
    squash_kernel<<<128, 256>>>(out, 0);

    routing_kernel<<<dim3(NCHUNK, BB), 256>>>(0);
    squash_kernel<<<128, 256>>>(out, 1);

    routing_kernel<<<dim3(NCHUNK, BB), 256>>>(0);
    squash_kernel<<<128, 256>>>(out, 2);
}

// round 4
// speedup vs baseline: 1.1657x; 1.1657x over previous
#include <cuda_runtime.h>
#include <cuda_fp16.h>

#define BB 64
#define II 4096
#define CC 32
#define DD 16
#define KD 16

#define NCHUNK 32      // i-chunks for routing partials
#define RITERS 16      // i's per warp per routing CTA: NCHUNK*8*RITERS == II
#define WP 20          // Wsm pitch (floats) -> conflict-free B-fragment LDS
#define XP 20          // xsm pitch (floats) -> conflict-free A-fragment LDS

// Scratch (static device globals; no runtime allocation)
__device__ __half g_uhat[(size_t)BB * II * CC * DD];   // 268 MB, layout [b][i][n=c*16+D]
__device__ float  g_spart[NCHUNK][BB * CC * DD];       // partial s, layout [chunk][b][D][c]
__device__ float  g_V[BB * CC * DD];                   // Vsum, layout [b][c][D]

static __device__ __forceinline__ unsigned f2tf32(float a) {
    unsigned r;
    asm("cvt.rna.tf32.f32 %0, %1;" : "=r"(r) : "f"(a));
    return r;
}

// ---------- pass 0 (tensor cores, v2): u_hat[b,i,n] = sum_d x[b,i,d] * W[i,n,d] ----------
// CTA = (i, half): 256 threads = 8 warps, covers all 64 b x 256 n (n-half of 512).
// warp = (mt 0..3, ng 0..1): rows 16*mt..+15, cols 128*ng..+127 (16 n-tiles of 8).
// m16n8k8 tf32 mma; direct fragment->global fp16 stores (no smem epilogue).
__global__ __launch_bounds__(256) void uhat_kernel(
    const float* __restrict__ x, const float* __restrict__ w) {
    __shared__ float Wsm[256 * WP];   // [n_local*WP + d], tf32 bits
    __shared__ float xsm[BB * XP];    // [b*XP + d],       tf32 bits

    const int tid  = threadIdx.x;
    const int i    = blockIdx.x >> 1;
    const int half = blockIdx.x & 1;
    const int warp = tid >> 5;
    const int l    = tid & 31;
    const int lr   = l >> 2;     // 0..7
    const int lc   = l & 3;      // 0..3
    const int mt   = warp >> 1;  // 0..3
    const int ng   = warp & 1;   // 0..1

    // ---- load W slab (256 n x 16 d) + full x tile (64 b x 16 d), cvt to tf32 ----
    {
        const float4* w4 = (const float4*)(w + (size_t)i * 8192 + half * 4096);
        #pragma unroll
        for (int q = 0; q < 4; q++) {
            int t_ = tid + q * 256;            // float4 index
            float4 v = w4[t_];
            int n = t_ >> 2, d0 = (t_ & 3) * 4;
            float4 cv;
            cv.x = __uint_as_float(f2tf32(v.x));
            cv.y = __uint_as_float(f2tf32(v.y));
            cv.z = __uint_as_float(f2tf32(v.z));
            cv.w = __uint_as_float(f2tf32(v.w));
            *(float4*)&Wsm[n * WP + d0] = cv;
        }
        #pragma unroll
        for (int q = 0; q < 4; q++) {
            int e = tid + q * 256;             // (b,d)
            float v = x[((size_t)(e >> 4)) * (II * KD) + (size_t)i * KD + (e & 15)];
            xsm[(e >> 4) * XP + (e & 15)] = __uint_as_float(f2tf32(v));
        }
    }
    __syncthreads();

    // ---- mma: 16 n-tiles x 2 k-steps ----
    float c[16][4];
    #pragma unroll
    for (int nt = 0; nt < 16; nt++)
        { c[nt][0] = 0.f; c[nt][1] = 0.f; c[nt][2] = 0.f; c[nt][3] = 0.f; }

    #pragma unroll
    for (int ks = 0; ks < 2; ks++) {
        int xoff = (16 * mt + lr) * XP + 8 * ks + lc;
        unsigned a0 = __float_as_uint(xsm[xoff]);
        unsigned a1 = __float_as_uint(xsm[xoff + 8 * XP]);
        unsigned a2 = __float_as_uint(xsm[xoff + 4]);
        unsigned a3 = __float_as_uint(xsm[xoff + 8 * XP + 4]);
        #pragma unroll
        for (int nt = 0; nt < 16; nt++) {
            int woff = (128 * ng + 8 * nt + lr) * WP + 8 * ks + lc;
            unsigned b0 = __float_as_uint(Wsm[woff]);
            unsigned b1 = __float_as_uint(Wsm[woff + 4]);
            asm volatile(
                "mma.sync.aligned.m16n8k8.row.col.f32.tf32.tf32.f32 "
                "{%0,%1,%2,%3}, {%4,%5,%6,%7}, {%8,%9}, {%0,%1,%2,%3};"
                : "+f"(c[nt][0]), "+f"(c[nt][1]), "+f"(c[nt][2]), "+f"(c[nt][3])
                : "r"(a0), "r"(a1), "r"(a2), "r"(a3), "r"(b0), "r"(b1));
        }
    }

    // ---- direct fp16 stores: c0,c1 -> (row0, col..col+1); c2,c3 -> (row0+8, ...) ----
    {
        const int b0   = 16 * mt + lr;
        const int colb = 256 * half + 128 * ng + 2 * lc;
        __half* d0 = g_uhat + ((size_t)b0 * II + i) * (CC * DD) + colb;
        __half* d1 = d0 + (size_t)8 * II * (CC * DD);   // row b0+8
        #pragma unroll
        for (int nt = 0; nt < 16; nt++) {
            *(__half2*)(d0 + 8 * nt) = __floats2half2_rn(c[nt][0], c[nt][1]);
            *(__half2*)(d1 + 8 * nt) = __floats2half2_rn(c[nt][2], c[nt][3]);
        }
    }
}

// ---------- routing pass: s[b,c,D] = sum_i softmax_c(u . Vsum) * u ----------
__global__ __launch_bounds__(256) void routing_kernel(int pass1) {
    const int b     = blockIdx.y;
    const int chunk = blockIdx.x;
    const int warp  = threadIdx.x >> 5;
    const int c     = threadIdx.x & 31;

    float V[DD];
    if (!pass1) {
        #pragma unroll
        for (int D = 0; D < DD; D++) V[D] = g_V[(b * CC + c) * DD + D];
    }

    float sacc[DD];
    #pragma unroll
    for (int D = 0; D < DD; D++) sacc[D] = 0.0f;

    const int i0 = chunk * (8 * RITERS) + warp * RITERS;
    const uint4* p = (const uint4*)(g_uhat + ((size_t)b * II + i0) * (CC * DD)) + c * 2;

    uint4 q0 = p[0];
    uint4 q1 = p[1];

    #pragma unroll 4
    for (int k = 0; k < RITERS; k++) {
        uint4 n0 = q0, n1 = q1;
        if (k + 1 < RITERS) {
            n0 = p[(k + 1) * 64];
            n1 = p[(k + 1) * 64 + 1];
        }

        float u[DD];
        unsigned rr[8] = {q0.x, q0.y, q0.z, q0.w, q1.x, q1.y, q1.z, q1.w};
        #pragma unroll
        for (int pp = 0; pp < 8; pp++) {
            __half2 h = *reinterpret_cast<__half2*>(&rr[pp]);
            float2 f = __half22float2(h);
            u[2 * pp]     = f.x;
            u[2 * pp + 1] = f.y;
        }

        float cij;
        if (pass1) {
            cij = 1.0f / 32.0f;
        } else {
            float logit = 0.0f;
            #pragma unroll
            for (int D = 0; D < DD; D++) logit = fmaf(u[D], V[D], logit);
            float m = logit;
            #pragma unroll
            for (int off = 16; off > 0; off >>= 1)
                m = fmaxf(m, __shfl_xor_sync(0xffffffffu, m, off));
            float e = __expf(logit - m);
            float ssum = e;
            #pragma unroll
            for (int off = 16; off > 0; off >>= 1)
                ssum += __shfl_xor_sync(0xffffffffu, ssum, off);
            cij = e / ssum;
        }

        #pragma unroll
        for (int D = 0; D < DD; D++) sacc[D] = fmaf(cij, u[D], sacc[D]);

        q0 = n0; q1 = n1;
    }

    __shared__ float red[8][CC * DD];
    #pragma unroll
    for (int D = 0; D < DD; D++) red[warp][D * 32 + c] = sacc[D];
    __syncthreads();

    for (int t = threadIdx.x; t < CC * DD; t += 256) {
        float v = 0.0f;
        #pragma unroll
        for (int wq = 0; wq < 8; wq++) v += red[wq][t];
        g_spart[chunk][b * (CC * DD) + t] = v;   // [chunk][b][D][c]
    }
}

// ---------- squash: one thread per (b,c,D); 16-lane shfl for |s|^2 ----------
__global__ void squash_kernel(float* __restrict__ out, int pass) {
    int t = blockIdx.x * blockDim.x + threadIdx.x;   // (b,c,D), D fastest
    int bc = t >> 4, D = t & 15;
    int b = bc >> 5, c = bc & 31;
    int addr = b * (CC * DD) + D * 32 + c;           // [b][D][c] partial layout

    float s = 0.0f;
    #pragma unroll
    for (int ch = 0; ch < NCHUNK; ch++) s += g_spart[ch][addr];

    float sq = s * s;
    #pragma unroll
    for (int off = 1; off < 16; off <<= 1)
        sq += __shfl_xor_sync(0xffffffffu, sq, off);

    float f = 1.0f / ((1.0f + sq) * sqrtf(sq + 1e-9f));
    float v = s * f;

    if (pass == 0)      g_V[t] = v;
    else if (pass == 1) g_V[t] += v;
    else                out[t] = v;
}

extern "C" void kernel_launch(void* const* d_in, const int* in_sizes, int n_in,
                              void* d_out, int out_size) {
    const float* x = (const float*)d_in[0];
    const float* w = (const float*)d_in[1];
    float* out = (float*)d_out;

    uhat_kernel<<<II * 2, 256>>>(x, w);

    routing_kernel<<<dim3(NCHUNK, BB), 256>>>(1);
    squash_kernel<<<128, 256>>>(out, 0);

    routing_kernel<<<dim3(NCHUNK, BB), 256>>>(0);
    squash_kernel<<<128, 256>>>(out, 1);

    routing_kernel<<<dim3(NCHUNK, BB), 256>>>(0);
    squash_kernel<<<128, 256>>>(out, 2);
}

// round 5
// speedup vs baseline: 2.0705x; 1.7763x over previous
#include <cuda_runtime.h>
#include <cuda_fp16.h>

#define BB 64
#define II 4096
#define CC 32
#define DD 16
#define KD 16

#define NCHUNK 32      // i-chunks for routing partials
#define RITERS 16      // i's per warp per routing CTA: NCHUNK*8*RITERS == II
#define WP 20          // Wsm pitch (floats) -> conflict-free B-fragment LDS
#define XP 20          // xsm pitch (floats) -> conflict-free A-fragment LDS
#define OPH 264        // Osm pitch in halfs (132 words == 4 mod 32: conflict-free)

// Scratch (static device globals; no runtime allocation)
__device__ __half g_uhat[(size_t)BB * II * CC * DD];   // 268 MB, layout [b][i][n=c*16+D]
__device__ float  g_spart[NCHUNK][BB * CC * DD];       // partial s, layout [chunk][b][D][c]
__device__ float  g_V[BB * CC * DD];                   // Vsum, layout [b][c][D]

static __device__ __forceinline__ unsigned f2tf32(float a) {
    unsigned r;
    asm("cvt.rna.tf32.f32 %0, %1;" : "=r"(r) : "f"(a));
    return r;
}

// ---------- pass 0 (tensor cores, v3): u_hat[b,i,n] = sum_d x[b,i,d] * W[i,n,d] ----------
// CTA = (i, half): 256 threads = 8 warps, covers 64 b x 256 n (n-half of 512).
// warp = (mt 0..3, ng 0..1). m16n8k8 tf32 mma.
// Epilogue: fragments -> Osm (fp16, conflict-free banks) -> fully coalesced 512B/row stores.
__global__ __launch_bounds__(256) void uhat_kernel(
    const float* __restrict__ x, const float* __restrict__ w) {
    __shared__ float  Wsm[256 * WP];   // [n_local*WP + d], tf32 bits
    __shared__ float  xsm[BB * XP];    // [b*XP + d],       tf32 bits
    __shared__ __half Osm[BB * OPH];   // [b*OPH + n_local]

    const int tid  = threadIdx.x;
    const int i    = blockIdx.x >> 1;
    const int half = blockIdx.x & 1;
    const int warp = tid >> 5;
    const int l    = tid & 31;
    const int lr   = l >> 2;     // 0..7
    const int lc   = l & 3;      // 0..3
    const int mt   = warp >> 1;  // 0..3
    const int ng   = warp & 1;   // 0..1

    // ---- load W slab (256 n x 16 d) + full x tile (64 b x 16 d), cvt to tf32 ----
    {
        const float4* w4 = (const float4*)(w + (size_t)i * 8192 + half * 4096);
        #pragma unroll
        for (int q = 0; q < 4; q++) {
            int t_ = tid + q * 256;            // float4 index
            float4 v = w4[t_];
            int n = t_ >> 2, d0 = (t_ & 3) * 4;
            float4 cv;
            cv.x = __uint_as_float(f2tf32(v.x));
            cv.y = __uint_as_float(f2tf32(v.y));
            cv.z = __uint_as_float(f2tf32(v.z));
            cv.w = __uint_as_float(f2tf32(v.w));
            *(float4*)&Wsm[n * WP + d0] = cv;
        }
        #pragma unroll
        for (int q = 0; q < 4; q++) {
            int e = tid + q * 256;             // (b,d)
            float v = x[((size_t)(e >> 4)) * (II * KD) + (size_t)i * KD + (e & 15)];
            xsm[(e >> 4) * XP + (e & 15)] = __uint_as_float(f2tf32(v));
        }
    }
    __syncthreads();

    // ---- mma: 16 n-tiles x 2 k-steps ----
    float c[16][4];
    #pragma unroll
    for (int nt = 0; nt < 16; nt++)
        { c[nt][0] = 0.f; c[nt][1] = 0.f; c[nt][2] = 0.f; c[nt][3] = 0.f; }

    #pragma unroll
    for (int ks = 0; ks < 2; ks++) {
        int xoff = (16 * mt + lr) * XP + 8 * ks + lc;
        unsigned a0 = __float_as_uint(xsm[xoff]);
        unsigned a1 = __float_as_uint(xsm[xoff + 8 * XP]);
        unsigned a2 = __float_as_uint(xsm[xoff + 4]);
        unsigned a3 = __float_as_uint(xsm[xoff + 8 * XP + 4]);
        #pragma unroll
        for (int nt = 0; nt < 16; nt++) {
            int woff = (128 * ng + 8 * nt + lr) * WP + 8 * ks + lc;
            unsigned b0 = __float_as_uint(Wsm[woff]);
            unsigned b1 = __float_as_uint(Wsm[woff + 4]);
            asm volatile(
                "mma.sync.aligned.m16n8k8.row.col.f32.tf32.tf32.f32 "
                "{%0,%1,%2,%3}, {%4,%5,%6,%7}, {%8,%9}, {%0,%1,%2,%3};"
                : "+f"(c[nt][0]), "+f"(c[nt][1]), "+f"(c[nt][2]), "+f"(c[nt][3])
                : "r"(a0), "r"(a1), "r"(a2), "r"(a3), "r"(b0), "r"(b1));
        }
    }

    // ---- epilogue: fragments -> Osm (bank = 4*lr + 4*nt + lc mod 32: conflict-free) ----
    {
        int r0 = 16 * mt + lr, r1 = r0 + 8;
        int nb = 128 * ng + 2 * lc;
        #pragma unroll
        for (int nt = 0; nt < 16; nt++) {
            *(__half2*)&Osm[r0 * OPH + nb + 8 * nt] = __floats2half2_rn(c[nt][0], c[nt][1]);
            *(__half2*)&Osm[r1 * OPH + nb + 8 * nt] = __floats2half2_rn(c[nt][2], c[nt][3]);
        }
    }
    __syncthreads();

    // ---- store: warp w owns rows 8w..8w+7; per row the warp stores 512B contiguous ----
    {
        __half* base = g_uhat + (size_t)i * (CC * DD) + 256 * half + l * 8;
        #pragma unroll
        for (int r = 0; r < 8; r++) {
            int b = 8 * warp + r;
            uint4 v = *(uint4*)&Osm[b * OPH + l * 8];          // LDS.128, stride-4 phases
            *(uint4*)(base + (size_t)b * II * (CC * DD)) = v;  // STG.128, 4 lines/warp
        }
    }
}

// ---------- routing pass: s[b,c,D] = sum_i softmax_c(u . Vsum) * u ----------
__global__ __launch_bounds__(256) void routing_kernel(int pass1) {
    const int b     = blockIdx.y;
    const int chunk = blockIdx.x;
    const int warp  = threadIdx.x >> 5;
    const int c     = threadIdx.x & 31;

    float V[DD];
    if (!pass1) {
        #pragma unroll
        for (int D = 0; D < DD; D++) V[D] = g_V[(b * CC + c) * DD + D];
    }

    float sacc[DD];
    #pragma unroll
    for (int D = 0; D < DD; D++) sacc[D] = 0.0f;

    const int i0 = chunk * (8 * RITERS) + warp * RITERS;
    const uint4* p = (const uint4*)(g_uhat + ((size_t)b * II + i0) * (CC * DD)) + c * 2;

    uint4 q0 = p[0];
    uint4 q1 = p[1];

    #pragma unroll 4
    for (int k = 0; k < RITERS; k++) {
        uint4 n0 = q0, n1 = q1;
        if (k + 1 < RITERS) {
            n0 = p[(k + 1) * 64];
            n1 = p[(k + 1) * 64 + 1];
        }

        float u[DD];
        unsigned rr[8] = {q0.x, q0.y, q0.z, q0.w, q1.x, q1.y, q1.z, q1.w};
        #pragma unroll
        for (int pp = 0; pp < 8; pp++) {
            __half2 h = *reinterpret_cast<__half2*>(&rr[pp]);
            float2 f = __half22float2(h);
            u[2 * pp]     = f.x;
            u[2 * pp + 1] = f.y;
        }

        float cij;
        if (pass1) {
            cij = 1.0f / 32.0f;
        } else {
            float logit = 0.0f;
            #pragma unroll
            for (int D = 0; D < DD; D++) logit = fmaf(u[D], V[D], logit);
            float m = logit;
            #pragma unroll
            for (int off = 16; off > 0; off >>= 1)
                m = fmaxf(m, __shfl_xor_sync(0xffffffffu, m, off));
            float e = __expf(logit - m);
            float ssum = e;
            #pragma unroll
            for (int off = 16; off > 0; off >>= 1)
                ssum += __shfl_xor_sync(0xffffffffu, ssum, off);
            cij = e / ssum;
        }

        #pragma unroll
        for (int D = 0; D < DD; D++) sacc[D] = fmaf(cij, u[D], sacc[D]);

        q0 = n0; q1 = n1;
    }

    __shared__ float red[8][CC * DD];
    #pragma unroll
    for (int D = 0; D < DD; D++) red[warp][D * 32 + c] = sacc[D];
    __syncthreads();

    for (int t = threadIdx.x; t < CC * DD; t += 256) {
        float v = 0.0f;
        #pragma unroll
        for (int wq = 0; wq < 8; wq++) v += red[wq][t];
        g_spart[chunk][b * (CC * DD) + t] = v;   // [chunk][b][D][c]
    }
}

// ---------- squash: one thread per (b,c,D); 16-lane shfl for |s|^2 ----------
__global__ void squash_kernel(float* __restrict__ out, int pass) {
    int t = blockIdx.x * blockDim.x + threadIdx.x;   // (b,c,D), D fastest
    int bc = t >> 4, D = t & 15;
    int b = bc >> 5, c = bc & 31;
    int addr = b * (CC * DD) + D * 32 + c;           // [b][D][c] partial layout

    float s = 0.0f;
    #pragma unroll
    for (int ch = 0; ch < NCHUNK; ch++) s += g_spart[ch][addr];

    float sq = s * s;
    #pragma unroll
    for (int off = 1; off < 16; off <<= 1)
        sq += __shfl_xor_sync(0xffffffffu, sq, off);

    float f = 1.0f / ((1.0f + sq) * sqrtf(sq + 1e-9f));
    float v = s * f;

    if (pass == 0)      g_V[t] = v;
    else if (pass == 1) g_V[t] += v;
    else                out[t] = v;
}

extern "C" void kernel_launch(void* const* d_in, const int* in_sizes, int n_in,
                              void* d_out, int out_size) {
    const float* x = (const float*)d_in[0];
    const float* w = (const float*)d_in[1];
    float* out = (float*)d_out;

    uhat_kernel<<<II * 2, 256>>>(x, w);

    routing_kernel<<<dim3(NCHUNK, BB), 256>>>(1);
    squash_kernel<<<128, 256>>>(out, 0);

    routing_kernel<<<dim3(NCHUNK, BB), 256>>>(0);
    squash_kernel<<<128, 256>>>(out, 1);

    routing_kernel<<<dim3(NCHUNK, BB), 256>>>(0);
    squash_kernel<<<128, 256>>>(out, 2);
}